// round 4
// baseline (speedup 1.0000x reference)
#include <cuda_runtime.h>
#include <cstddef>

// Problem constants
#define CI 256
#define CO 128
#define NX 16          // input spatial extent
#define YD 33          // intermediate y spatial extent
#define YD2 (33*33)    // 1089
#define YD3 (33*33*33) // 35937

// Intermediate y [8][128][33][33][33] and transposed weights [27][256][128]
__device__ float g_y[8 * 128 * YD3];        // ~147 MB
__device__ float g_wt[27 * CI * CO];        // ~3.5 MB

// ---------------------------------------------------------------------------
// Weight prep: g_wt[(j*CI + ci)*CO + co] = w[(co*CI + ci)*27 + j]
// Writes coalesced; one-time scattered reads are tiny (884736 elements).
// ---------------------------------------------------------------------------
__global__ void wprep_kernel(const float* __restrict__ w) {
    int i = blockIdx.x * 256 + threadIdx.x;
    if (i >= 27 * CI * CO) return;
    int co = i & (CO - 1);
    int r  = i >> 7;
    int ci = r & (CI - 1);
    int j  = r >> 8;
    g_wt[i] = __ldg(&w[(co * CI + ci) * 27 + j]);
}

// ---------------------------------------------------------------------------
// Stage 1: fractionally-strided conv, decomposed by output parity.
//   y[2q+s] per axis:  s==0 (even): w[0]*x[q-1] + w[2]*x[q]
//                      s==1 (odd):  w[1]*x[q]
// Template <SA,SB,SC> = parity per axis -> compile-time tap structure.
// Block tile: 4(a) x 4(b) x 8(c) q-positions x all 128 co.
// 256 threads: lane -> (b = lane>>3, c = lane&7), warp-id -> 16-co group,
// each thread accumulates acc[4 a][16 co].
// ---------------------------------------------------------------------------
template <int SA, int SB, int SC>
__global__ void __launch_bounds__(256, 2)
stage1_kernel(const float* __restrict__ x) {
    constexpr int NTA = SA ? 1 : 2, NTB = SB ? 1 : 2, NTC = SC ? 1 : 2;
    constexpr int NT  = NTA * NTB * NTC;            // taps per voxel
    constexpr int EA  = SA ? 16 : 17;               // output extent (q) per axis
    constexpr int EB  = SB ? 16 : 17;
    constexpr int EC  = SC ? 16 : 17;
    constexpr int WSA = SA ? 4 : 5;                 // x window per axis
    constexpr int WSB = SB ? 4 : 5;
    constexpr int WSC = SC ? 8 : 9;
    constexpr int TLB = SB ? 4 : 5;                 // tile counts (grid decode)
    constexpr int TLC = SC ? 2 : 3;

    __shared__ float Xs[4][WSA][WSB][WSC];
    __shared__ float Ws[4][NT][CO];

    const int n   = blockIdx.y;
    const int bid = blockIdx.x;
    const int tct = bid % TLC;
    const int tbt = (bid / TLC) % TLB;
    const int tat = bid / (TLC * TLB);
    const int q0a = tat * 4, q0b = tbt * 4, q0c = tct * 8;

    const int tid  = threadIdx.x;
    const int lane = tid & 31;
    const int co0  = (tid >> 5) * 16;   // warp-uniform -> Ws broadcast
    const int bpos = lane >> 3;         // 0..3
    const int cpos = lane & 7;          // 0..7

    const float* xn = x + (size_t)n * CI * (NX * NX * NX);

    float acc[4][16];
    #pragma unroll
    for (int a = 0; a < 4; a++)
        #pragma unroll
        for (int u = 0; u < 16; u++) acc[a][u] = 0.0f;

    for (int ci0 = 0; ci0 < CI; ci0 += 4) {
        __syncthreads();
        // ---- fill x window (zero-padded at borders) ----
        constexpr int XE = 4 * WSA * WSB * WSC;
        for (int e = tid; e < XE; e += 256) {
            int c  = e % WSC; int r = e / WSC;
            int b  = r % WSB; r /= WSB;
            int a  = r % WSA; int cc = r / WSA;
            int xa = q0a - (SA ? 0 : 1) + a;
            int xb = q0b - (SB ? 0 : 1) + b;
            int xc = q0c - (SC ? 0 : 1) + c;
            float v = 0.0f;
            if ((unsigned)xa < 16u && (unsigned)xb < 16u && (unsigned)xc < 16u)
                v = __ldg(xn + (size_t)(ci0 + cc) * 4096 + xa * 256 + xb * 16 + xc);
            Xs[cc][a][b][c] = v;
        }
        // ---- fill weights for this group's taps (coalesced over co) ----
        constexpr int WE = 4 * NT * CO;
        for (int e = tid; e < WE; e += 256) {
            int co = e & (CO - 1);
            int r  = e >> 7;
            int tp = r % NT; int cc = r / NT;
            int tcc = tp % NTC;
            int tbb = (tp / NTC) % NTB;
            int taa = tp / (NTC * NTB);
            int wa = SA ? 1 : 2 * taa;
            int wb = SB ? 1 : 2 * tbb;
            int wc = SC ? 1 : 2 * tcc;
            Ws[cc][tp][co] =
                g_wt[(size_t)((wa * 3 + wb) * 3 + wc) * (CI * CO) + (ci0 + cc) * CO + co];
        }
        __syncthreads();

        // ---- FMA core: per (ci, tap): 4 x-LDS + 16 w-LDS(broadcast) -> 64 FMA
        #pragma unroll
        for (int cc = 0; cc < 4; cc++) {
            #pragma unroll
            for (int tp = 0; tp < NT; tp++) {
                const int tcc = tp % NTC;
                const int tbb = (tp / NTC) % NTB;
                const int taa = tp / (NTC * NTB);
                float xv[4];
                #pragma unroll
                for (int a = 0; a < 4; a++)
                    xv[a] = Xs[cc][a + taa][bpos + tbb][cpos + tcc];
                #pragma unroll
                for (int u = 0; u < 16; u++) {
                    float wv = Ws[cc][tp][co0 + u];
                    #pragma unroll
                    for (int a = 0; a < 4; a++)
                        acc[a][u] = fmaf(xv[a], wv, acc[a][u]);
                }
            }
        }
    }

    // ---- store to y[n][co][2qa+SA][2qb+SB][2qc+SC] ----
    const int qb = q0b + bpos, qc = q0c + cpos;
    if (qb < EB && qc < EC) {
        const int tb2 = 2 * qb + SB, tc2 = 2 * qc + SC;
        #pragma unroll
        for (int a = 0; a < 4; a++) {
            int qa = q0a + a;
            if (qa < EA) {
                int ta2 = 2 * qa + SA;
                size_t base = (size_t)(n * CO + co0) * YD3 + ta2 * YD2 + tb2 * YD + tc2;
                #pragma unroll
                for (int u = 0; u < 16; u++)
                    g_y[base + (size_t)u * YD3] = acc[a][u];
            }
        }
    }
}

// ---------------------------------------------------------------------------
// Stage 2: separable FIR [0.25,0.75,0.75,0.25] per axis, pad(1,1), + bias.
// out[u] = sum_d k[d] * y[u-1+d] along each axis (kernel symmetric).
// Block: one (n, co, 8x8x8 output tile); 11^3 y window in smem, 3 passes.
// ---------------------------------------------------------------------------
__global__ void __launch_bounds__(256)
stage2_kernel(const float* __restrict__ bias, float* __restrict__ out) {
    __shared__ float ys[11 * 11 * 11];
    __shared__ float t1[11 * 11 * 8];
    __shared__ float t2[11 * 8 * 8];

    const int t   = blockIdx.x;          // 0..63
    const int u0c = (t & 3) * 8;
    const int u0b = ((t >> 2) & 3) * 8;
    const int u0a = (t >> 4) * 8;
    const int co  = blockIdx.y;
    const int n   = blockIdx.z;
    const int tid = threadIdx.x;

    const float* yb = g_y + (size_t)(n * CO + co) * YD3;

    for (int e = tid; e < 1331; e += 256) {
        int c = e % 11; int r = e / 11;
        int b = r % 11; int a = r / 11;
        int ta2 = u0a - 1 + a, tb2 = u0b - 1 + b, tc2 = u0c - 1 + c;
        float v = 0.0f;
        if ((unsigned)ta2 < 33u && (unsigned)tb2 < 33u && (unsigned)tc2 < 33u)
            v = yb[(size_t)ta2 * YD2 + tb2 * YD + tc2];
        ys[e] = v;
    }
    __syncthreads();

    // pass over c: 11 x 11 x 8
    for (int e = tid; e < 11 * 11 * 8; e += 256) {
        int c = e & 7; int r = e >> 3;
        int b = r % 11; int a = r / 11;
        const float* p = &ys[(a * 11 + b) * 11 + c];
        t1[e] = 0.25f * (p[0] + p[3]) + 0.75f * (p[1] + p[2]);
    }
    __syncthreads();

    // pass over b: 11 x 8 x 8
    for (int e = tid; e < 11 * 8 * 8; e += 256) {
        int c = e & 7; int b = (e >> 3) & 7; int a = e >> 6;
        const float* p = &t1[(a * 11 + b) * 8 + c];
        t2[e] = 0.25f * (p[0] + p[3 * 8]) + 0.75f * (p[8] + p[2 * 8]);
    }
    __syncthreads();

    const float bv = __ldg(&bias[co]);
    // pass over a: 8 x 8 x 8, write out
    for (int e = tid; e < 8 * 8 * 8; e += 256) {
        int c = e & 7; int b = (e >> 3) & 7; int a = e >> 6;
        const float* p = &t2[(a * 8 + b) * 8 + c];
        float v = 0.25f * (p[0] + p[3 * 64]) + 0.75f * (p[64] + p[2 * 64]) + bv;
        out[(size_t)(n * CO + co) * 32768 +
            (size_t)(u0a + a) * 1024 + (u0b + b) * 32 + (u0c + c)] = v;
    }
}

// ---------------------------------------------------------------------------
extern "C" void kernel_launch(void* const* d_in, const int* in_sizes, int n_in,
                              void* d_out, int out_size) {
    (void)in_sizes; (void)n_in; (void)out_size;
    const float* x    = (const float*)d_in[0];
    const float* w    = (const float*)d_in[1];
    const float* bias = (const float*)d_in[2];
    float* out        = (float*)d_out;

    wprep_kernel<<<(27 * CI * CO + 255) / 256, 256>>>(w);

    stage1_kernel<0, 0, 0><<<dim3(5 * 5 * 3, 8), 256>>>(x);
    stage1_kernel<0, 0, 1><<<dim3(5 * 5 * 2, 8), 256>>>(x);
    stage1_kernel<0, 1, 0><<<dim3(5 * 4 * 3, 8), 256>>>(x);
    stage1_kernel<0, 1, 1><<<dim3(5 * 4 * 2, 8), 256>>>(x);
    stage1_kernel<1, 0, 0><<<dim3(4 * 5 * 3, 8), 256>>>(x);
    stage1_kernel<1, 0, 1><<<dim3(4 * 5 * 2, 8), 256>>>(x);
    stage1_kernel<1, 1, 0><<<dim3(4 * 4 * 3, 8), 256>>>(x);
    stage1_kernel<1, 1, 1><<<dim3(4 * 4 * 2, 8), 256>>>(x);

    stage2_kernel<<<dim3(64, CO, 8), 256>>>(bias, out);
}

// round 8
// speedup vs baseline: 3.9256x; 3.9256x over previous
#include <cuda_runtime.h>
#include <cstdint>
#include <cstddef>

#define CI 256
#define CO 128
#define YD 33
#define YD2 (33*33)
#define YD3 (33*33*33)

// ---------------------------------------------------------------------------
// Device global scratch
// ---------------------------------------------------------------------------
__device__ float g_y[8 * 128 * YD3];                 // intermediate y (~147 MB)
__device__ float g_xa[(size_t)8 * 4096 * 256];       // A: x^T [n][p][ci], tf32-rounded (33.5 MB)
__device__ float g_wbb[27 * 128 * 256];              // B: [j][co][ci], tf32-rounded (3.5 MB)
__device__ float g_Z[(size_t)8 * 27 * 128 * 4096];   // Z [n][j][co][p] (~453 MB)

// ---------------------------------------------------------------------------
// Helpers
// ---------------------------------------------------------------------------
__device__ __forceinline__ uint32_t smem_u32(const void* p) {
    uint32_t a;
    asm("{ .reg .u64 t; cvta.to.shared.u64 t, %1; cvt.u32.u64 %0, t; }" : "=r"(a) : "l"(p));
    return a;
}
__device__ __forceinline__ float tf32r(float v) {
    uint32_t o; asm("cvt.rna.tf32.f32 %0, %1;" : "=r"(o) : "f"(v));
    return __uint_as_float(o);
}
#define CP16(dst_u32, src_ptr) \
    asm volatile("cp.async.cg.shared.global [%0], [%1], 16;" :: "r"(dst_u32), "l"(src_ptr))
#define CP_COMMIT() asm volatile("cp.async.commit_group;" ::: "memory")
#define CP_WAIT(n)  asm volatile("cp.async.wait_group %0;" :: "n"(n) : "memory")

// m16n8k8 tf32 MMA (legacy HMMA path — baseline PTX, works on plain sm_103)
__device__ __forceinline__ void mma8(float* c, const uint32_t* a, const uint32_t* b) {
    asm volatile("mma.sync.aligned.m16n8k8.row.col.f32.tf32.tf32.f32 "
                 "{%0,%1,%2,%3}, {%4,%5,%6,%7}, {%8,%9}, {%0,%1,%2,%3};"
                 : "+f"(c[0]), "+f"(c[1]), "+f"(c[2]), "+f"(c[3])
                 : "r"(a[0]), "r"(a[1]), "r"(a[2]), "r"(a[3]), "r"(b[0]), "r"(b[1]));
}

// Swizzled smem index: 16 floats (4x16B units) per row; unit ^= (row & 3).
__device__ __forceinline__ int sw_idx(int row, int k) {
    return row * 16 + (((k >> 2) ^ (row & 3)) << 2) + (k & 3);
}

// ---------------------------------------------------------------------------
// A prep: g_xa[n][p][ci] = tf32(x[n][ci][p]).  32x32 smem transpose tiles.
// ---------------------------------------------------------------------------
__global__ void __launch_bounds__(256) xa_kernel(const float* __restrict__ x) {
    __shared__ float t[32][33];
    const int pt = blockIdx.x, ct = blockIdx.y, n = blockIdx.z;
    const int tx = threadIdx.x & 31, ty = threadIdx.x >> 5;
    const float* xb = x + ((size_t)n * CI + ct * 32) * 4096 + pt * 32;
    #pragma unroll
    for (int i = 0; i < 4; i++)
        t[ty + i * 8][tx] = __ldg(xb + (size_t)(ty + i * 8) * 4096 + tx);
    __syncthreads();
    float* ob = g_xa + ((size_t)n * 4096 + pt * 32) * 256 + ct * 32;
    #pragma unroll
    for (int i = 0; i < 4; i++)
        ob[(size_t)(ty + i * 8) * 256 + tx] = tf32r(t[tx][ty + i * 8]);
}

// ---------------------------------------------------------------------------
// B prep: g_wbb[j][co][ci] = tf32(w[co][ci][j]).
// ---------------------------------------------------------------------------
__global__ void __launch_bounds__(256) wb_kernel(const float* __restrict__ w) {
    int i = blockIdx.x * 256 + threadIdx.x;          // 27*128*256 total
    if (i >= 27 * 128 * 256) return;
    int ci = i & 255;
    int co = (i >> 8) & 127;
    int j  = i >> 15;
    g_wbb[i] = tf32r(__ldg(&w[((size_t)co * CI + ci) * 27 + j]));
}

// ---------------------------------------------------------------------------
// GEMM: Z[n][j][co][p] = sum_ci A[p][ci]*B[co][ci].
// CTA 128x128xK256; 8 warps = 4(M)x2(N); warp tile 32x64; K chunks of 16,
// double-buffered cp.async; tf32 mma.sync.m16n8k8.
// ---------------------------------------------------------------------------
__global__ void __launch_bounds__(256) gemm_kernel() {
    __shared__ float sA[2][128 * 16];
    __shared__ float sB[2][128 * 16];

    const int tid = threadIdx.x, wid = tid >> 5, lane = tid & 31;
    const int pt = blockIdx.x, j = blockIdx.y, n = blockIdx.z;
    const int wm = wid >> 1, wn = wid & 1;
    const int g = lane >> 2, tig = lane & 3;
    const int m0 = wm * 32, n0 = wn * 64;

    const float* Ab = g_xa + ((size_t)n * 4096 + pt * 128) * 256;
    const float* Bb = g_wbb + (size_t)j * (128 * 256);

    const uint32_t saA = smem_u32(sA), saB = smem_u32(sB);

    // per-thread cp.async slots: 2 x 16B for A, 2 for B
    const int v0 = tid, v1 = tid + 256;
    const int r0 = v0 >> 2, u0 = v0 & 3, r1 = v1 >> 2, u1 = v1 & 3;
    const uint32_t dA0 = (uint32_t)(r0 * 16 + ((u0 ^ (r0 & 3)) << 2)) * 4;
    const uint32_t dA1 = (uint32_t)(r1 * 16 + ((u1 ^ (r1 & 3)) << 2)) * 4;

    float acc[2][8][4];
    #pragma unroll
    for (int a = 0; a < 2; a++)
        #pragma unroll
        for (int b = 0; b < 8; b++)
            #pragma unroll
            for (int c = 0; c < 4; c++) acc[a][b][c] = 0.0f;

    // preload chunk 0
    {
        const float* As = Ab; const float* Bs = Bb;
        CP16(saA + dA0, As + (size_t)r0 * 256 + u0 * 4);
        CP16(saA + dA1, As + (size_t)r1 * 256 + u1 * 4);
        CP16(saB + dA0, Bs + (size_t)r0 * 256 + u0 * 4);
        CP16(saB + dA1, Bs + (size_t)r1 * 256 + u1 * 4);
        CP_COMMIT();
    }

    int buf = 0;
    for (int kc = 0; kc < 16; kc++) {
        if (kc + 1 < 16) {
            const float* As = Ab + (kc + 1) * 16;
            const float* Bs = Bb + (kc + 1) * 16;
            const uint32_t oA = saA + (buf ^ 1) * 8192;
            const uint32_t oB = saB + (buf ^ 1) * 8192;
            CP16(oA + dA0, As + (size_t)r0 * 256 + u0 * 4);
            CP16(oA + dA1, As + (size_t)r1 * 256 + u1 * 4);
            CP16(oB + dA0, Bs + (size_t)r0 * 256 + u0 * 4);
            CP16(oB + dA1, Bs + (size_t)r1 * 256 + u1 * 4);
            CP_COMMIT();
            CP_WAIT(1);
        } else {
            CP_WAIT(0);
        }
        __syncthreads();

        const uint32_t* sAb = (const uint32_t*)sA[buf];
        const uint32_t* sBb = (const uint32_t*)sB[buf];
        #pragma unroll
        for (int ks = 0; ks < 2; ks++) {
            const int kb = ks * 8;
            uint32_t af[2][4];
            #pragma unroll
            for (int mt = 0; mt < 2; mt++) {
                int r = m0 + mt * 16 + g;
                af[mt][0] = sAb[sw_idx(r,     kb + tig)];
                af[mt][1] = sAb[sw_idx(r + 8, kb + tig)];
                af[mt][2] = sAb[sw_idx(r,     kb + tig + 4)];
                af[mt][3] = sAb[sw_idx(r + 8, kb + tig + 4)];
            }
            #pragma unroll
            for (int nt = 0; nt < 8; nt++) {
                int nn = n0 + nt * 8 + g;
                uint32_t bf[2];
                bf[0] = sBb[sw_idx(nn, kb + tig)];
                bf[1] = sBb[sw_idx(nn, kb + tig + 4)];
                mma8(acc[0][nt], af[0], bf);
                mma8(acc[1][nt], af[1], bf);
            }
        }
        __syncthreads();
        buf ^= 1;
    }

    // Epilogue: c0:(p, co) c1:(p, co+1) c2:(p+8, co) c3:(p+8, co+1)
    float* Zb = g_Z + (size_t)((n * 27 + j) * 128) * 4096 + (size_t)pt * 128;
    #pragma unroll
    for (int mt = 0; mt < 2; mt++) {
        #pragma unroll
        for (int nt = 0; nt < 8; nt++) {
            int p  = m0 + mt * 16 + g;
            int co = n0 + nt * 8 + 2 * tig;
            Zb[(size_t)co * 4096 + p]           = acc[mt][nt][0];
            Zb[(size_t)(co + 1) * 4096 + p]     = acc[mt][nt][1];
            Zb[(size_t)co * 4096 + p + 8]       = acc[mt][nt][2];
            Zb[(size_t)(co + 1) * 4096 + p + 8] = acc[mt][nt][3];
        }
    }
}

// ---------------------------------------------------------------------------
// y-build: y[t] = sum over (j,p) with t = 2p + 2 - j per axis.
//   t odd  -> (j=1, p=(t-1)/2)
//   t even -> (j=0, p=(t-2)/2) if t>=2;  (j=2, p=t/2) if t<=30
// ---------------------------------------------------------------------------
__device__ __forceinline__ int plist(int t, int* j, int* p) {
    if (t & 1) { j[0] = 1; p[0] = (t - 1) >> 1; return 1; }
    int n = 0;
    if (t >= 2)  { j[n] = 0; p[n] = (t - 2) >> 1; n++; }
    if (t <= 30) { j[n] = 2; p[n] = t >> 1;       n++; }
    return n;
}

__global__ void __launch_bounds__(256) ybuild_kernel() {
    const int bx = blockIdx.x;
    const int co = bx & 127, n = bx >> 7;
    const float* Zb = g_Z + (size_t)(n * 27 * 128 + co) * 4096;
    const size_t FLD = (size_t)128 * 4096;
    float* yb = g_y + (size_t)(n * CO + co) * YD3;

    for (int e = threadIdx.x; e < YD3; e += 256) {
        int tc = e % 33; int r = e / 33;
        int tb = r % 33; int ta = r / 33;
        int ja[2], pa[2], jb[2], pb[2], jc[2], pc[2];
        int na = plist(ta, ja, pa);
        int nb = plist(tb, jb, pb);
        int nc = plist(tc, jc, pc);
        float s = 0.0f;
        for (int ia = 0; ia < na; ia++)
            for (int ib = 0; ib < nb; ib++)
                for (int ic = 0; ic < nc; ic++)
                    s += __ldg(&Zb[(size_t)((ja[ia] * 3 + jb[ib]) * 3 + jc[ic]) * FLD
                                   + pa[ia] * 256 + pb[ib] * 16 + pc[ic]]);
        yb[e] = s;
    }
}

// ---------------------------------------------------------------------------
// Stage 2: separable FIR [0.25,0.75,0.75,0.25] per axis + bias (proven).
// ---------------------------------------------------------------------------
__global__ void __launch_bounds__(256)
stage2_kernel(const float* __restrict__ bias, float* __restrict__ out) {
    __shared__ float ys[11 * 11 * 11];
    __shared__ float t1[11 * 11 * 8];
    __shared__ float t2[11 * 8 * 8];

    const int t   = blockIdx.x;
    const int u0c = (t & 3) * 8;
    const int u0b = ((t >> 2) & 3) * 8;
    const int u0a = (t >> 4) * 8;
    const int co  = blockIdx.y;
    const int n   = blockIdx.z;
    const int tid = threadIdx.x;

    const float* yb = g_y + (size_t)(n * CO + co) * YD3;

    for (int e = tid; e < 1331; e += 256) {
        int c = e % 11; int r = e / 11;
        int b = r % 11; int a = r / 11;
        int ta2 = u0a - 1 + a, tb2 = u0b - 1 + b, tc2 = u0c - 1 + c;
        float v = 0.0f;
        if ((unsigned)ta2 < 33u && (unsigned)tb2 < 33u && (unsigned)tc2 < 33u)
            v = yb[(size_t)ta2 * YD2 + tb2 * YD + tc2];
        ys[e] = v;
    }
    __syncthreads();

    for (int e = tid; e < 11 * 11 * 8; e += 256) {
        int c = e & 7; int r = e >> 3;
        int b = r % 11; int a = r / 11;
        const float* p = &ys[(a * 11 + b) * 11 + c];
        t1[e] = 0.25f * (p[0] + p[3]) + 0.75f * (p[1] + p[2]);
    }
    __syncthreads();

    for (int e = tid; e < 11 * 8 * 8; e += 256) {
        int c = e & 7; int b = (e >> 3) & 7; int a = e >> 6;
        const float* p = &t1[(a * 11 + b) * 8 + c];
        t2[e] = 0.25f * (p[0] + p[3 * 8]) + 0.75f * (p[8] + p[2 * 8]);
    }
    __syncthreads();

    const float bv = __ldg(&bias[co]);
    for (int e = tid; e < 8 * 8 * 8; e += 256) {
        int c = e & 7; int b = (e >> 3) & 7; int a = e >> 6;
        const float* p = &t2[(a * 8 + b) * 8 + c];
        float v = 0.25f * (p[0] + p[3 * 64]) + 0.75f * (p[64] + p[2 * 64]) + bv;
        out[(size_t)(n * CO + co) * 32768 +
            (size_t)(u0a + a) * 1024 + (u0b + b) * 32 + (u0c + c)] = v;
    }
}

// ---------------------------------------------------------------------------
extern "C" void kernel_launch(void* const* d_in, const int* in_sizes, int n_in,
                              void* d_out, int out_size) {
    (void)in_sizes; (void)n_in; (void)out_size;
    const float* x    = (const float*)d_in[0];
    const float* w    = (const float*)d_in[1];
    const float* bias = (const float*)d_in[2];
    float* out        = (float*)d_out;

    xa_kernel<<<dim3(128, 8, 8), 256>>>(x);
    wb_kernel<<<(27 * 128 * 256 + 255) / 256, 256>>>(w);
    gemm_kernel<<<dim3(32, 27, 8), 256>>>();
    ybuild_kernel<<<1024, 256>>>();
    stage2_kernel<<<dim3(64, CO, 8), 256>>>(bias, out);
}

// round 10
// speedup vs baseline: 5.5084x; 1.4032x over previous
#include <cuda_runtime.h>
#include <cuda_fp16.h>
#include <cstdint>
#include <cstddef>

#define CI 256
#define CO 128
#define YD 33
#define YD2 (33*33)
#define YD3 (33*33*33)

// ---------------------------------------------------------------------------
// Device global scratch
// ---------------------------------------------------------------------------
__device__ float  g_y[8 * 128 * YD3];                 // intermediate y (~147 MB)
__device__ __half g_xa[(size_t)8 * 4096 * 256];       // A: x^T [n][p][ci] fp16 (16.8 MB)
__device__ __half g_wbb[27 * 128 * 256];              // B: [j][co][ci] fp16 (1.8 MB)
__device__ float  g_Z[(size_t)8 * 27 * 4096 * 128];   // Z [n][j][p][co] (~453 MB)

// ---------------------------------------------------------------------------
// Helpers
// ---------------------------------------------------------------------------
__device__ __forceinline__ uint32_t smem_u32(const void* p) {
    uint32_t a;
    asm("{ .reg .u64 t; cvta.to.shared.u64 t, %1; cvt.u32.u64 %0, t; }" : "=r"(a) : "l"(p));
    return a;
}
#define CP16(dst_u32, src_ptr) \
    asm volatile("cp.async.cg.shared.global [%0], [%1], 16;" :: "r"(dst_u32), "l"(src_ptr))
#define CP_COMMIT() asm volatile("cp.async.commit_group;" ::: "memory")
#define CP_WAIT(n)  asm volatile("cp.async.wait_group %0;" :: "n"(n) : "memory")

// m16n8k16 fp16 MMA, fp32 accumulate (baseline PTX; works on plain sm_103)
__device__ __forceinline__ void mma16(float* c, const uint32_t* a, const uint32_t* b) {
    asm volatile("mma.sync.aligned.m16n8k16.row.col.f32.f16.f16.f32 "
                 "{%0,%1,%2,%3}, {%4,%5,%6,%7}, {%8,%9}, {%0,%1,%2,%3};"
                 : "+f"(c[0]), "+f"(c[1]), "+f"(c[2]), "+f"(c[3])
                 : "r"(a[0]), "r"(a[1]), "r"(a[2]), "r"(a[3]), "r"(b[0]), "r"(b[1]));
}

// ---------------------------------------------------------------------------
// A prep: g_xa[n][p][ci] = fp16(x[n][ci][p]).  32x32 smem transpose tiles.
// ---------------------------------------------------------------------------
__global__ void __launch_bounds__(256) xa_kernel(const float* __restrict__ x) {
    __shared__ float t[32][33];
    const int pt = blockIdx.x, ct = blockIdx.y, n = blockIdx.z;
    const int tx = threadIdx.x & 31, ty = threadIdx.x >> 5;
    const float* xb = x + ((size_t)n * CI + ct * 32) * 4096 + pt * 32;
    #pragma unroll
    for (int i = 0; i < 4; i++)
        t[ty + i * 8][tx] = __ldg(xb + (size_t)(ty + i * 8) * 4096 + tx);
    __syncthreads();
    __half* ob = g_xa + ((size_t)n * 4096 + pt * 32) * 256 + ct * 32;
    #pragma unroll
    for (int i = 0; i < 4; i++)
        ob[(size_t)(ty + i * 8) * 256 + tx] = __float2half_rn(t[tx][ty + i * 8]);
}

// ---------------------------------------------------------------------------
// B prep: g_wbb[j][co][ci] = fp16(w[co][ci][j]).
// ---------------------------------------------------------------------------
__global__ void __launch_bounds__(256) wb_kernel(const float* __restrict__ w) {
    int i = blockIdx.x * 256 + threadIdx.x;          // 27*128*256 total
    if (i >= 27 * 128 * 256) return;
    int ci = i & 255;
    int co = (i >> 8) & 127;
    int j  = i >> 15;
    g_wbb[i] = __float2half_rn(__ldg(&w[((size_t)co * CI + ci) * 27 + j]));
}

// ---------------------------------------------------------------------------
// GEMM: Z[n][j][p][co] = sum_ci A[p][ci]*B[co][ci].
// CTA 128x128xK256; 8 warps = 4(M)x2(N); warp tile 32x64; K chunks of 32,
// double-buffered cp.async; fp16 mma.sync.m16n8k16, fp32 accum.
// Smem rows padded to 80B (40 halves) -> conflict-free LDS, no swizzle.
// ---------------------------------------------------------------------------
__global__ void __launch_bounds__(256) gemm_kernel() {
    __shared__ __align__(16) __half sA[2][128 * 40];   // 20 KB
    __shared__ __align__(16) __half sB[2][128 * 40];   // 20 KB

    const int tid = threadIdx.x, wid = tid >> 5, lane = tid & 31;
    const int pt = blockIdx.x, j = blockIdx.y, n = blockIdx.z;
    const int wm = wid >> 1, wn = wid & 1;
    const int g = lane >> 2, tig = lane & 3;
    const int m0 = wm * 32, n0 = wn * 64;

    const __half* Ab = g_xa + ((size_t)n * 4096 + pt * 128) * 256;
    const __half* Bb = g_wbb + (size_t)j * (128 * 256);

    const uint32_t saA = smem_u32(sA), saB = smem_u32(sB);

    // cp.async slots: 512 16B-units per operand per chunk; 2 per thread each.
    const int v0 = tid, v1 = tid + 256;
    const int r0 = v0 >> 2, u0 = v0 & 3, r1 = v1 >> 2, u1 = v1 & 3;
    const uint32_t d0 = (uint32_t)(r0 * 80 + u0 * 16);
    const uint32_t d1 = (uint32_t)(r1 * 80 + u1 * 16);

    float acc[2][8][4];
    #pragma unroll
    for (int a = 0; a < 2; a++)
        #pragma unroll
        for (int b = 0; b < 8; b++)
            #pragma unroll
            for (int c = 0; c < 4; c++) acc[a][b][c] = 0.0f;

    // preload chunk 0
    CP16(saA + d0, Ab + (size_t)r0 * 256 + u0 * 8);
    CP16(saA + d1, Ab + (size_t)r1 * 256 + u1 * 8);
    CP16(saB + d0, Bb + (size_t)r0 * 256 + u0 * 8);
    CP16(saB + d1, Bb + (size_t)r1 * 256 + u1 * 8);
    CP_COMMIT();

    int buf = 0;
    for (int kc = 0; kc < 8; kc++) {
        if (kc + 1 < 8) {
            const __half* As = Ab + (kc + 1) * 32;
            const __half* Bs = Bb + (kc + 1) * 32;
            const uint32_t oA = saA + (buf ^ 1) * 10240;
            const uint32_t oB = saB + (buf ^ 1) * 10240;
            CP16(oA + d0, As + (size_t)r0 * 256 + u0 * 8);
            CP16(oA + d1, As + (size_t)r1 * 256 + u1 * 8);
            CP16(oB + d0, Bs + (size_t)r0 * 256 + u0 * 8);
            CP16(oB + d1, Bs + (size_t)r1 * 256 + u1 * 8);
            CP_COMMIT();
            CP_WAIT(1);
        } else {
            CP_WAIT(0);
        }
        __syncthreads();

        const __half* sAb = sA[buf];
        const __half* sBb = sB[buf];
        #pragma unroll
        for (int ks = 0; ks < 2; ks++) {
            const int kb = ks * 16;
            uint32_t af[2][4];
            #pragma unroll
            for (int mt = 0; mt < 2; mt++) {
                int r = m0 + mt * 16 + g;
                af[mt][0] = *(const uint32_t*)&sAb[r * 40 + kb + 2 * tig];
                af[mt][1] = *(const uint32_t*)&sAb[(r + 8) * 40 + kb + 2 * tig];
                af[mt][2] = *(const uint32_t*)&sAb[r * 40 + kb + 2 * tig + 8];
                af[mt][3] = *(const uint32_t*)&sAb[(r + 8) * 40 + kb + 2 * tig + 8];
            }
            #pragma unroll
            for (int nt = 0; nt < 8; nt++) {
                int nn = n0 + nt * 8 + g;
                uint32_t bf[2];
                bf[0] = *(const uint32_t*)&sBb[nn * 40 + kb + 2 * tig];
                bf[1] = *(const uint32_t*)&sBb[nn * 40 + kb + 2 * tig + 8];
                mma16(acc[0][nt], af[0], bf);
                mma16(acc[1][nt], af[1], bf);
            }
        }
        __syncthreads();
        buf ^= 1;
    }

    // Epilogue: Z[n][j][p][co], float2 per (p,co pair). Lane-quad (tig 0..3)
    // covers co..co+7 = one full 32B sector per p-row -> 100% sector use.
    float* Zb = g_Z + ((size_t)(n * 27 + j) * 4096 + (size_t)pt * 128) * 128;
    #pragma unroll
    for (int mt = 0; mt < 2; mt++) {
        #pragma unroll
        for (int nt = 0; nt < 8; nt++) {
            int p  = m0 + mt * 16 + g;
            int co = n0 + nt * 8 + 2 * tig;
            *(float2*)&Zb[(size_t)p * 128 + co] =
                make_float2(acc[mt][nt][0], acc[mt][nt][1]);
            *(float2*)&Zb[(size_t)(p + 8) * 128 + co] =
                make_float2(acc[mt][nt][2], acc[mt][nt][3]);
        }
    }
}

// ---------------------------------------------------------------------------
// y-build: y[t] = sum over (j,p) with t = 2p + 2 - j per axis.
//   t odd  -> (j=1, p=(t-1)/2)
//   t even -> (j=0, p=(t-2)/2) if t>=2;  (j=2, p=t/2) if t<=30
// Block = (ta, tb, n); lanes run along co -> all Z reads 128B-coalesced.
// Results staged [co][tc] in smem, written out along tc (coalesced).
// ---------------------------------------------------------------------------
__device__ __forceinline__ int plist(int t, int* j, int* p) {
    if (t & 1) { j[0] = 1; p[0] = (t - 1) >> 1; return 1; }
    int n = 0;
    if (t >= 2)  { j[n] = 0; p[n] = (t - 2) >> 1; n++; }
    if (t <= 30) { j[n] = 2; p[n] = t >> 1;       n++; }
    return n;
}

__global__ void __launch_bounds__(256) ybuild_kernel() {
    __shared__ float yt[128][34];
    const int ta = blockIdx.x, tb = blockIdx.y, n = blockIdx.z;
    const int tid = threadIdx.x;
    const int co = tid & 127, half = tid >> 7;

    int ja[2], pa[2], jb[2], pb[2];
    const int na = plist(ta, ja, pa);
    const int nb = plist(tb, jb, pb);
    const float* Zn = g_Z + (size_t)n * 27 * 4096 * 128;

    for (int tc = half; tc < 33; tc += 2) {
        int jc[2], pc[2];
        int nc = plist(tc, jc, pc);
        float s = 0.0f;
        for (int ia = 0; ia < na; ia++)
            for (int ib = 0; ib < nb; ib++)
                for (int ic = 0; ic < nc; ic++) {
                    int f = (ja[ia] * 3 + jb[ib]) * 3 + jc[ic];
                    int p = pa[ia] * 256 + pb[ib] * 16 + pc[ic];
                    s += __ldg(&Zn[((size_t)f * 4096 + p) * 128 + co]);
                }
        yt[co][tc] = s;
    }
    __syncthreads();

    const int wid = tid >> 5, lane = tid & 31;
    float* yb = g_y + (size_t)n * 128 * YD3 + (size_t)ta * YD2 + tb * YD;
    for (int r = wid; r < 128; r += 8)
        for (int tc = lane; tc < 33; tc += 32)
            yb[(size_t)r * YD3 + tc] = yt[r][tc];
}

// ---------------------------------------------------------------------------
// Stage 2: separable FIR [0.25,0.75,0.75,0.25] per axis + bias (proven).
// ---------------------------------------------------------------------------
__global__ void __launch_bounds__(256)
stage2_kernel(const float* __restrict__ bias, float* __restrict__ out) {
    __shared__ float ys[11 * 11 * 11];
    __shared__ float t1[11 * 11 * 8];
    __shared__ float t2[11 * 8 * 8];

    const int t   = blockIdx.x;
    const int u0c = (t & 3) * 8;
    const int u0b = ((t >> 2) & 3) * 8;
    const int u0a = (t >> 4) * 8;
    const int co  = blockIdx.y;
    const int n   = blockIdx.z;
    const int tid = threadIdx.x;

    const float* yb = g_y + (size_t)(n * CO + co) * YD3;

    for (int e = tid; e < 1331; e += 256) {
        int c = e % 11; int r = e / 11;
        int b = r % 11; int a = r / 11;
        int ta2 = u0a - 1 + a, tb2 = u0b - 1 + b, tc2 = u0c - 1 + c;
        float v = 0.0f;
        if ((unsigned)ta2 < 33u && (unsigned)tb2 < 33u && (unsigned)tc2 < 33u)
            v = yb[(size_t)ta2 * YD2 + tb2 * YD + tc2];
        ys[e] = v;
    }
    __syncthreads();

    for (int e = tid; e < 11 * 11 * 8; e += 256) {
        int c = e & 7; int r = e >> 3;
        int b = r % 11; int a = r / 11;
        const float* p = &ys[(a * 11 + b) * 11 + c];
        t1[e] = 0.25f * (p[0] + p[3]) + 0.75f * (p[1] + p[2]);
    }
    __syncthreads();

    for (int e = tid; e < 11 * 8 * 8; e += 256) {
        int c = e & 7; int b = (e >> 3) & 7; int a = e >> 6;
        const float* p = &t1[(a * 11 + b) * 8 + c];
        t2[e] = 0.25f * (p[0] + p[3 * 8]) + 0.75f * (p[8] + p[2 * 8]);
    }
    __syncthreads();

    const float bv = __ldg(&bias[co]);
    for (int e = tid; e < 8 * 8 * 8; e += 256) {
        int c = e & 7; int b = (e >> 3) & 7; int a = e >> 6;
        const float* p = &t2[(a * 8 + b) * 8 + c];
        float v = 0.25f * (p[0] + p[3 * 64]) + 0.75f * (p[64] + p[2 * 64]) + bv;
        out[(size_t)(n * CO + co) * 32768 +
            (size_t)(u0a + a) * 1024 + (u0b + b) * 32 + (u0c + c)] = v;
    }
}

// ---------------------------------------------------------------------------
extern "C" void kernel_launch(void* const* d_in, const int* in_sizes, int n_in,
                              void* d_out, int out_size) {
    (void)in_sizes; (void)n_in; (void)out_size;
    const float* x    = (const float*)d_in[0];
    const float* w    = (const float*)d_in[1];
    const float* bias = (const float*)d_in[2];
    float* out        = (float*)d_out;

    xa_kernel<<<dim3(128, 8, 8), 256>>>(x);
    wb_kernel<<<(27 * 128 * 256 + 255) / 256, 256>>>(w);
    gemm_kernel<<<dim3(32, 27, 8), 256>>>();
    ybuild_kernel<<<dim3(33, 33, 8), 256>>>();
    stage2_kernel<<<dim3(64, CO, 8), 256>>>(bias, out);
}

// round 14
// speedup vs baseline: 7.5838x; 1.3768x over previous
#include <cuda_runtime.h>
#include <cuda_fp16.h>
#include <cstdint>
#include <cstddef>

#define CI 256
#define CO 128
#define YD 33
#define YD2 (33*33)
#define YD3 (33*33*33)

// ---------------------------------------------------------------------------
// Device global scratch
// ---------------------------------------------------------------------------
__device__ __align__(16) float  g_y[8 * 128 * YD3];               // ~147 MB
__device__ __align__(16) __half g_xa[(size_t)8 * 4096 * 256];     // A fp16
__device__ __align__(16) __half g_wbb[27 * 128 * 256];            // B fp16
__device__ __align__(16) float  g_Z[(size_t)8 * 27 * 4096 * 128]; // ~453 MB

// ---------------------------------------------------------------------------
// Helpers
// ---------------------------------------------------------------------------
__device__ __forceinline__ uint32_t smem_u32(const void* p) {
    uint32_t a;
    asm("{ .reg .u64 t; cvta.to.shared.u64 t, %1; cvt.u32.u64 %0, t; }" : "=r"(a) : "l"(p));
    return a;
}
#define CP16(dst_u32, src_ptr) \
    asm volatile("cp.async.cg.shared.global [%0], [%1], 16;" :: "r"(dst_u32), "l"(src_ptr))
#define CP_COMMIT() asm volatile("cp.async.commit_group;" ::: "memory")
#define CP_WAIT(n)  asm volatile("cp.async.wait_group %0;" :: "n"(n) : "memory")

__device__ __forceinline__ void mma16(float* c, const uint32_t* a, const uint32_t* b) {
    asm volatile("mma.sync.aligned.m16n8k16.row.col.f32.f16.f16.f32 "
                 "{%0,%1,%2,%3}, {%4,%5,%6,%7}, {%8,%9}, {%0,%1,%2,%3};"
                 : "+f"(c[0]), "+f"(c[1]), "+f"(c[2]), "+f"(c[3])
                 : "r"(a[0]), "r"(a[1]), "r"(a[2]), "r"(a[3]), "r"(b[0]), "r"(b[1]));
}

// ---------------------------------------------------------------------------
// A prep: g_xa[n][p][ci] = fp16(x[n][ci][p]).
// ---------------------------------------------------------------------------
__global__ void __launch_bounds__(256) xa_kernel(const float* __restrict__ x) {
    __shared__ float t[32][33];
    const int pt = blockIdx.x, ct = blockIdx.y, n = blockIdx.z;
    const int tx = threadIdx.x & 31, ty = threadIdx.x >> 5;
    const float* xb = x + ((size_t)n * CI + ct * 32) * 4096 + pt * 32;
    #pragma unroll
    for (int i = 0; i < 4; i++)
        t[ty + i * 8][tx] = __ldg(xb + (size_t)(ty + i * 8) * 4096 + tx);
    __syncthreads();
    __half* ob = g_xa + ((size_t)n * 4096 + pt * 32) * 256 + ct * 32;
    #pragma unroll
    for (int i = 0; i < 4; i++)
        ob[(size_t)(ty + i * 8) * 256 + tx] = __float2half_rn(t[tx][ty + i * 8]);
}

// ---------------------------------------------------------------------------
// B prep: g_wbb[j][co][ci] = fp16(w[co][ci][j]).
// ---------------------------------------------------------------------------
__global__ void __launch_bounds__(256) wb_kernel(const float* __restrict__ w) {
    int i = blockIdx.x * 256 + threadIdx.x;
    if (i >= 27 * 128 * 256) return;
    int ci = i & 255;
    int co = (i >> 8) & 127;
    int j  = i >> 15;
    g_wbb[i] = __float2half_rn(__ldg(&w[((size_t)co * CI + ci) * 27 + j]));
}

// ---------------------------------------------------------------------------
// GEMM: Z[n][j][p][co] = sum_ci A[p][ci]*B[co][ci].  (unchanged, proven)
// ---------------------------------------------------------------------------
__global__ void __launch_bounds__(256) gemm_kernel() {
    __shared__ __align__(16) __half sA[2][128 * 40];
    __shared__ __align__(16) __half sB[2][128 * 40];

    const int tid = threadIdx.x, wid = tid >> 5, lane = tid & 31;
    const int pt = blockIdx.x, j = blockIdx.y, n = blockIdx.z;
    const int wm = wid >> 1, wn = wid & 1;
    const int g = lane >> 2, tig = lane & 3;
    const int m0 = wm * 32, n0 = wn * 64;

    const __half* Ab = g_xa + ((size_t)n * 4096 + pt * 128) * 256;
    const __half* Bb = g_wbb + (size_t)j * (128 * 256);

    const uint32_t saA = smem_u32(sA), saB = smem_u32(sB);

    const int v0 = tid, v1 = tid + 256;
    const int r0 = v0 >> 2, u0 = v0 & 3, r1 = v1 >> 2, u1 = v1 & 3;
    const uint32_t d0 = (uint32_t)(r0 * 80 + u0 * 16);
    const uint32_t d1 = (uint32_t)(r1 * 80 + u1 * 16);

    float acc[2][8][4];
    #pragma unroll
    for (int a = 0; a < 2; a++)
        #pragma unroll
        for (int b = 0; b < 8; b++)
            #pragma unroll
            for (int c = 0; c < 4; c++) acc[a][b][c] = 0.0f;

    CP16(saA + d0, Ab + (size_t)r0 * 256 + u0 * 8);
    CP16(saA + d1, Ab + (size_t)r1 * 256 + u1 * 8);
    CP16(saB + d0, Bb + (size_t)r0 * 256 + u0 * 8);
    CP16(saB + d1, Bb + (size_t)r1 * 256 + u1 * 8);
    CP_COMMIT();

    int buf = 0;
    for (int kc = 0; kc < 8; kc++) {
        if (kc + 1 < 8) {
            const __half* As = Ab + (kc + 1) * 32;
            const __half* Bs = Bb + (kc + 1) * 32;
            const uint32_t oA = saA + (buf ^ 1) * 10240;
            const uint32_t oB = saB + (buf ^ 1) * 10240;
            CP16(oA + d0, As + (size_t)r0 * 256 + u0 * 8);
            CP16(oA + d1, As + (size_t)r1 * 256 + u1 * 8);
            CP16(oB + d0, Bs + (size_t)r0 * 256 + u0 * 8);
            CP16(oB + d1, Bs + (size_t)r1 * 256 + u1 * 8);
            CP_COMMIT();
            CP_WAIT(1);
        } else {
            CP_WAIT(0);
        }
        __syncthreads();

        const __half* sAb = sA[buf];
        const __half* sBb = sB[buf];
        #pragma unroll
        for (int ks = 0; ks < 2; ks++) {
            const int kb = ks * 16;
            uint32_t af[2][4];
            #pragma unroll
            for (int mt = 0; mt < 2; mt++) {
                int r = m0 + mt * 16 + g;
                af[mt][0] = *(const uint32_t*)&sAb[r * 40 + kb + 2 * tig];
                af[mt][1] = *(const uint32_t*)&sAb[(r + 8) * 40 + kb + 2 * tig];
                af[mt][2] = *(const uint32_t*)&sAb[r * 40 + kb + 2 * tig + 8];
                af[mt][3] = *(const uint32_t*)&sAb[(r + 8) * 40 + kb + 2 * tig + 8];
            }
            #pragma unroll
            for (int nt = 0; nt < 8; nt++) {
                int nn = n0 + nt * 8 + g;
                uint32_t bf[2];
                bf[0] = *(const uint32_t*)&sBb[nn * 40 + kb + 2 * tig];
                bf[1] = *(const uint32_t*)&sBb[nn * 40 + kb + 2 * tig + 8];
                mma16(acc[0][nt], af[0], bf);
                mma16(acc[1][nt], af[1], bf);
            }
        }
        __syncthreads();
        buf ^= 1;
    }

    float* Zb = g_Z + ((size_t)(n * 27 + j) * 4096 + (size_t)pt * 128) * 128;
    #pragma unroll
    for (int mt = 0; mt < 2; mt++) {
        #pragma unroll
        for (int nt = 0; nt < 8; nt++) {
            int p  = m0 + mt * 16 + g;
            int co = n0 + nt * 8 + 2 * tig;
            *(float2*)&Zb[(size_t)p * 128 + co] =
                make_float2(acc[mt][nt][0], acc[mt][nt][1]);
            *(float2*)&Zb[(size_t)(p + 8) * 128 + co] =
                make_float2(acc[mt][nt][2], acc[mt][nt][3]);
        }
    }
}

// ---------------------------------------------------------------------------
// y-build v3 (fixed): float4 gmem gathers along co, hoisted field bases.
// Z index = ((f*4096 + p)*128 + co); p = pa*256 + pb*16 + pc
//   -> base(f_ab, pa, pb) + jc*524288 + pc*128       (pc stride = 128!)
//   t odd  -> (j=1, p=(t-1)/2)
//   t even -> (j=0, p=(t-2)/2) if t>=2;  (j=2, p=t/2) if t<=30
// ---------------------------------------------------------------------------
__device__ __forceinline__ int plist(int t, int* j, int* p) {
    if (t & 1) { j[0] = 1; p[0] = (t - 1) >> 1; return 1; }
    int n = 0;
    if (t >= 2)  { j[n] = 0; p[n] = (t - 2) >> 1; n++; }
    if (t <= 30) { j[n] = 2; p[n] = t >> 1;       n++; }
    return n;
}

__global__ void __launch_bounds__(256) ybuild_kernel() {
    __shared__ float yt[33][133];
    const int ta = blockIdx.x, tb = blockIdx.y, n = blockIdx.z;
    const int tid  = threadIdx.x;
    const int q    = tid & 31;        // co quad: co = 4*q
    const int slot = tid >> 5;        // 0..7 tc slot

    int ja[2], pa[2], jb[2], pb[2];
    const int na = plist(ta, ja, pa);
    const int nb = plist(tb, jb, pb);

    const float* Zn = g_Z + (size_t)n * 27 * 4096 * 128 + q * 4;
    const float* base[4];
    int nab = 0;
    for (int ia = 0; ia < na; ia++)
        for (int ib = 0; ib < nb; ib++)
            base[nab++] = Zn + (size_t)(ja[ia] * 3 + jb[ib]) * 3 * 524288
                             + (size_t)(pa[ia] * 256 + pb[ib] * 16) * 128;

    for (int tc = slot; tc < 33; tc += 8) {
        int jc[2], pc[2];
        int nc = plist(tc, jc, pc);
        float4 s = make_float4(0.f, 0.f, 0.f, 0.f);
        for (int k = 0; k < nab; k++)
            #pragma unroll
            for (int ic = 0; ic < 2; ic++) {
                if (ic < nc) {
                    float4 v = __ldg((const float4*)(base[k] +
                                     (size_t)jc[ic] * 524288 + (size_t)pc[ic] * 128));
                    s.x += v.x; s.y += v.y; s.z += v.z; s.w += v.w;
                }
            }
        // scalar STS: row stride 133 floats is conflict-free on the transpose
        // read below but not 16B-aligned for odd tc -> no vector STS.
        yt[tc][q * 4 + 0] = s.x;
        yt[tc][q * 4 + 1] = s.y;
        yt[tc][q * 4 + 2] = s.z;
        yt[tc][q * 4 + 3] = s.w;
    }
    __syncthreads();

    const int wid = tid >> 5, lane = tid & 31;
    float* yb = g_y + (size_t)n * 128 * YD3 + (size_t)ta * YD2 + tb * YD;
    for (int r = wid; r < 128; r += 8)
        for (int tc = lane; tc < 33; tc += 32)
            yb[(size_t)r * YD3 + tc] = yt[tc][r];
}

// ---------------------------------------------------------------------------
// Stage 2 v2: 16^3 out tile per (n,co); 19^3 window; separable FIR + bias.
// t2 aliases the dead ys buffer; dynamic smem = (6859 + 5776) floats.
// ---------------------------------------------------------------------------
__global__ void __launch_bounds__(256)
stage2_kernel(const float* __restrict__ bias, float* __restrict__ out) {
    extern __shared__ float sm[];
    float* ys = sm;            // 19*19*19 = 6859   (reused as t2: 19*16*16)
    float* t1 = sm + 6859;     // 19*19*16 = 5776

    const int tile = blockIdx.x;                    // 0..7
    const int u0c = (tile & 1) * 16;
    const int u0b = ((tile >> 1) & 1) * 16;
    const int u0a = (tile >> 2) * 16;
    const int co  = blockIdx.y;
    const int n   = blockIdx.z;
    const int tid = threadIdx.x;

    const float* yb = g_y + (size_t)(n * CO + co) * YD3;

    for (int e = tid; e < 6859; e += 256) {
        int c = e % 19; int r = e / 19;
        int b = r % 19; int a = r / 19;
        int ta2 = u0a - 1 + a, tb2 = u0b - 1 + b, tc2 = u0c - 1 + c;
        float v = 0.0f;
        if ((unsigned)ta2 < 33u && (unsigned)tb2 < 33u && (unsigned)tc2 < 33u)
            v = yb[(size_t)ta2 * YD2 + tb2 * YD + tc2];
        ys[e] = v;
    }
    __syncthreads();

    // pass c: t1[a][b][c16], 19*19*16
    for (int e = tid; e < 5776; e += 256) {
        int c = e & 15; int r = e >> 4;
        int b = r % 19; int a = r / 19;
        const float* p = &ys[(a * 19 + b) * 19 + c];
        t1[e] = 0.25f * (p[0] + p[3]) + 0.75f * (p[1] + p[2]);
    }
    __syncthreads();

    // pass b: t2[a][b16][c16] (aliased onto ys), 19*16*16
    for (int e = tid; e < 4864; e += 256) {
        int c = e & 15; int b = (e >> 4) & 15; int a = e >> 8;
        const float* p = &t1[(a * 19 + b) * 16 + c];
        ys[e] = 0.25f * (p[0] + p[3 * 16]) + 0.75f * (p[16] + p[2 * 16]);
    }
    __syncthreads();

    const float bv = __ldg(&bias[co]);
    // pass a: 16^3 out
    for (int e = tid; e < 4096; e += 256) {
        int c = e & 15; int b = (e >> 4) & 15; int a = e >> 8;
        const float* p = &ys[a * 256 + b * 16 + c];
        float v = 0.25f * (p[0] + p[3 * 256]) + 0.75f * (p[256] + p[2 * 256]) + bv;
        out[(size_t)(n * CO + co) * 32768 +
            (size_t)(u0a + a) * 1024 + (u0b + b) * 32 + (u0c + c)] = v;
    }
}

// ---------------------------------------------------------------------------
extern "C" void kernel_launch(void* const* d_in, const int* in_sizes, int n_in,
                              void* d_out, int out_size) {
    (void)in_sizes; (void)n_in; (void)out_size;
    const float* x    = (const float*)d_in[0];
    const float* w    = (const float*)d_in[1];
    const float* bias = (const float*)d_in[2];
    float* out        = (float*)d_out;

    const int s2_smem = (6859 + 5776) * 4;   // 50540 B
    cudaFuncSetAttribute(stage2_kernel,
                         cudaFuncAttributeMaxDynamicSharedMemorySize, s2_smem);

    xa_kernel<<<dim3(128, 8, 8), 256>>>(x);
    wb_kernel<<<(27 * 128 * 256 + 255) / 256, 256>>>(w);
    gemm_kernel<<<dim3(32, 27, 8), 256>>>();
    ybuild_kernel<<<dim3(33, 33, 8), 256>>>();
    stage2_kernel<<<dim3(8, CO, 8), 256, s2_smem>>>(bias, out);
}

// round 15
// speedup vs baseline: 8.6240x; 1.1372x over previous
#include <cuda_runtime.h>
#include <cuda_fp16.h>
#include <cstdint>
#include <cstddef>

#define CI 256
#define CO 128
#define YD 33
#define YD2 (33*33)
#define YD3 (33*33*33)

// ---------------------------------------------------------------------------
// Device global scratch
// ---------------------------------------------------------------------------
__device__ __align__(16) float  g_y[8 * 128 * YD3];                // ~147 MB
__device__ __align__(16) __half g_xa[(size_t)8 * 4096 * 256];      // A fp16
__device__ __align__(16) __half g_wbb[27 * 128 * 256];             // B fp16
__device__ __align__(16) __half g_Zh[(size_t)8 * 27 * 4096 * 128]; // Z fp16 (~226 MB)

// ---------------------------------------------------------------------------
// Helpers
// ---------------------------------------------------------------------------
__device__ __forceinline__ uint32_t smem_u32(const void* p) {
    uint32_t a;
    asm("{ .reg .u64 t; cvta.to.shared.u64 t, %1; cvt.u32.u64 %0, t; }" : "=r"(a) : "l"(p));
    return a;
}
#define CP16(dst_u32, src_ptr) \
    asm volatile("cp.async.cg.shared.global [%0], [%1], 16;" :: "r"(dst_u32), "l"(src_ptr))
#define CP_COMMIT() asm volatile("cp.async.commit_group;" ::: "memory")
#define CP_WAIT(n)  asm volatile("cp.async.wait_group %0;" :: "n"(n) : "memory")

__device__ __forceinline__ void mma16(float* c, const uint32_t* a, const uint32_t* b) {
    asm volatile("mma.sync.aligned.m16n8k16.row.col.f32.f16.f16.f32 "
                 "{%0,%1,%2,%3}, {%4,%5,%6,%7}, {%8,%9}, {%0,%1,%2,%3};"
                 : "+f"(c[0]), "+f"(c[1]), "+f"(c[2]), "+f"(c[3])
                 : "r"(a[0]), "r"(a[1]), "r"(a[2]), "r"(a[3]), "r"(b[0]), "r"(b[1]));
}
__device__ __forceinline__ void ldm_x4(uint32_t* r, uint32_t addr) {
    asm volatile("ldmatrix.sync.aligned.m8n8.x4.shared.b16 {%0,%1,%2,%3}, [%4];"
                 : "=r"(r[0]), "=r"(r[1]), "=r"(r[2]), "=r"(r[3]) : "r"(addr));
}

// ---------------------------------------------------------------------------
// A prep: g_xa[n][p][ci] = fp16(x[n][ci][p]).
// ---------------------------------------------------------------------------
__global__ void __launch_bounds__(256) xa_kernel(const float* __restrict__ x) {
    __shared__ float t[32][33];
    const int pt = blockIdx.x, ct = blockIdx.y, n = blockIdx.z;
    const int tx = threadIdx.x & 31, ty = threadIdx.x >> 5;
    const float* xb = x + ((size_t)n * CI + ct * 32) * 4096 + pt * 32;
    #pragma unroll
    for (int i = 0; i < 4; i++)
        t[ty + i * 8][tx] = __ldg(xb + (size_t)(ty + i * 8) * 4096 + tx);
    __syncthreads();
    __half* ob = g_xa + ((size_t)n * 4096 + pt * 32) * 256 + ct * 32;
    #pragma unroll
    for (int i = 0; i < 4; i++)
        ob[(size_t)(ty + i * 8) * 256 + tx] = __float2half_rn(t[tx][ty + i * 8]);
}

// ---------------------------------------------------------------------------
// B prep: g_wbb[j][co][ci] = fp16(w[co][ci][j]).
// ---------------------------------------------------------------------------
__global__ void __launch_bounds__(256) wb_kernel(const float* __restrict__ w) {
    int i = blockIdx.x * 256 + threadIdx.x;
    if (i >= 27 * 128 * 256) return;
    int ci = i & 255;
    int co = (i >> 8) & 127;
    int j  = i >> 15;
    g_wbb[i] = __float2half_rn(__ldg(&w[((size_t)co * CI + ci) * 27 + j]));
}

// ---------------------------------------------------------------------------
// GEMM: Zh[n][j][p][co] = fp16( sum_ci A[p][ci]*B[co][ci] ).
// CTA 128x128xK256; 8 warps = 4(M)x2(N); ldmatrix fragment loads; fp16 out.
// ---------------------------------------------------------------------------
__global__ void __launch_bounds__(256) gemm_kernel() {
    __shared__ __align__(16) __half sA[2][128 * 40];
    __shared__ __align__(16) __half sB[2][128 * 40];

    const int tid = threadIdx.x, wid = tid >> 5, lane = tid & 31;
    const int pt = blockIdx.x, j = blockIdx.y, n = blockIdx.z;
    const int wm = wid >> 1, wn = wid & 1;
    const int g = lane >> 2, tig = lane & 3;
    const int m0 = wm * 32, n0 = wn * 64;

    const __half* Ab = g_xa + ((size_t)n * 4096 + pt * 128) * 256;
    const __half* Bb = g_wbb + (size_t)j * (128 * 256);

    const uint32_t saA = smem_u32(sA), saB = smem_u32(sB);

    const int v0 = tid, v1 = tid + 256;
    const int r0 = v0 >> 2, u0 = v0 & 3, r1 = v1 >> 2, u1 = v1 & 3;
    const uint32_t d0 = (uint32_t)(r0 * 80 + u0 * 16);
    const uint32_t d1 = (uint32_t)(r1 * 80 + u1 * 16);

    // ldmatrix per-lane address components (in halves, x2 for bytes later):
    // A (x4, per mt): rows m0+mt*16+(lane&15), k-col offset (lane&16)?8:0
    const int arow = m0 + (lane & 15);
    const int akof = (lane & 16) ? 8 : 0;
    // B (x4, per nt-pair): rows n0+ntp*16+(lane&7)+((lane&16)?8:0), kof (lane&8)?8:0
    const int brow = n0 + (lane & 7) + ((lane & 16) ? 8 : 0);
    const int bkof = (lane & 8) ? 8 : 0;

    float acc[2][8][4];
    #pragma unroll
    for (int a = 0; a < 2; a++)
        #pragma unroll
        for (int b = 0; b < 8; b++)
            #pragma unroll
            for (int c = 0; c < 4; c++) acc[a][b][c] = 0.0f;

    CP16(saA + d0, Ab + (size_t)r0 * 256 + u0 * 8);
    CP16(saA + d1, Ab + (size_t)r1 * 256 + u1 * 8);
    CP16(saB + d0, Bb + (size_t)r0 * 256 + u0 * 8);
    CP16(saB + d1, Bb + (size_t)r1 * 256 + u1 * 8);
    CP_COMMIT();

    int buf = 0;
    for (int kc = 0; kc < 8; kc++) {
        if (kc + 1 < 8) {
            const __half* As = Ab + (kc + 1) * 32;
            const __half* Bs = Bb + (kc + 1) * 32;
            const uint32_t oA = saA + (buf ^ 1) * 10240;
            const uint32_t oB = saB + (buf ^ 1) * 10240;
            CP16(oA + d0, As + (size_t)r0 * 256 + u0 * 8);
            CP16(oA + d1, As + (size_t)r1 * 256 + u1 * 8);
            CP16(oB + d0, Bs + (size_t)r0 * 256 + u0 * 8);
            CP16(oB + d1, Bs + (size_t)r1 * 256 + u1 * 8);
            CP_COMMIT();
            CP_WAIT(1);
        } else {
            CP_WAIT(0);
        }
        __syncthreads();

        const uint32_t bA = saA + buf * 10240;
        const uint32_t bB = saB + buf * 10240;
        #pragma unroll
        for (int ks = 0; ks < 2; ks++) {
            const int kb = ks * 16;
            uint32_t af[2][4];
            #pragma unroll
            for (int mt = 0; mt < 2; mt++)
                ldm_x4(af[mt], bA + (uint32_t)(((arow + mt * 16) * 40 + kb + akof) * 2));
            uint32_t bf[4][4];   // [ntp][4] -> bf[ntp][0..1]=nt even, [2..3]=nt odd
            #pragma unroll
            for (int ntp = 0; ntp < 4; ntp++)
                ldm_x4(bf[ntp], bB + (uint32_t)(((brow + ntp * 16) * 40 + kb + bkof) * 2));
            #pragma unroll
            for (int nt = 0; nt < 8; nt++) {
                const uint32_t* bp = &bf[nt >> 1][(nt & 1) * 2];
                mma16(acc[0][nt], af[0], bp);
                mma16(acc[1][nt], af[1], bp);
            }
        }
        __syncthreads();
        buf ^= 1;
    }

    // Epilogue: fp16 half2 stores, Zh[n][j][p][co] (co even -> 4B aligned).
    __half* Zb = g_Zh + ((size_t)(n * 27 + j) * 4096 + (size_t)pt * 128) * 128;
    #pragma unroll
    for (int mt = 0; mt < 2; mt++) {
        #pragma unroll
        for (int nt = 0; nt < 8; nt++) {
            int p  = m0 + mt * 16 + g;
            int co = n0 + nt * 8 + 2 * tig;
            *(__half2*)&Zb[(size_t)p * 128 + co] =
                __floats2half2_rn(acc[mt][nt][0], acc[mt][nt][1]);
            *(__half2*)&Zb[(size_t)(p + 8) * 128 + co] =
                __floats2half2_rn(acc[mt][nt][2], acc[mt][nt][3]);
        }
    }
}

// ---------------------------------------------------------------------------
// y-build v4: fp16 Z, uint4 gathers = 8 co per load, hoisted field bases.
// Zh index = ((f*4096 + p)*128 + co); p = pa*256 + pb*16 + pc
//   t odd  -> (j=1, p=(t-1)/2)
//   t even -> (j=0, p=(t-2)/2) if t>=2;  (j=2, p=t/2) if t<=30
// Thread: o = co octet (co=8o), slot = tc slot (16 slots).
// ---------------------------------------------------------------------------
__device__ __forceinline__ int plist(int t, int* j, int* p) {
    if (t & 1) { j[0] = 1; p[0] = (t - 1) >> 1; return 1; }
    int n = 0;
    if (t >= 2)  { j[n] = 0; p[n] = (t - 2) >> 1; n++; }
    if (t <= 30) { j[n] = 2; p[n] = t >> 1;       n++; }
    return n;
}

__global__ void __launch_bounds__(256) ybuild_kernel() {
    __shared__ float yt[33][133];
    const int ta = blockIdx.x, tb = blockIdx.y, n = blockIdx.z;
    const int tid  = threadIdx.x;
    const int o    = tid & 15;        // co octet: co = 8*o
    const int slot = tid >> 4;        // 0..15 tc slot

    int ja[2], pa[2], jb[2], pb[2];
    const int na = plist(ta, ja, pa);
    const int nb = plist(tb, jb, pb);

    const __half* Zn = g_Zh + (size_t)n * 27 * 4096 * 128 + o * 8;
    const __half* base[4];
    int nab = 0;
    for (int ia = 0; ia < na; ia++)
        for (int ib = 0; ib < nb; ib++)
            base[nab++] = Zn + (size_t)(ja[ia] * 3 + jb[ib]) * 3 * 524288
                             + (size_t)(pa[ia] * 256 + pb[ib] * 16) * 128;

    for (int tc = slot; tc < 33; tc += 16) {
        int jc[2], pc[2];
        int nc = plist(tc, jc, pc);
        float s[8];
        #pragma unroll
        for (int i = 0; i < 8; i++) s[i] = 0.0f;
        for (int k = 0; k < nab; k++)
            #pragma unroll
            for (int ic = 0; ic < 2; ic++) {
                if (ic < nc) {
                    uint4 v = __ldg((const uint4*)(base[k] +
                                    (size_t)jc[ic] * 524288 + (size_t)pc[ic] * 128));
                    const __half2* h = (const __half2*)&v;
                    #pragma unroll
                    for (int i = 0; i < 4; i++) {
                        float2 f = __half22float2(h[i]);
                        s[2 * i]     += f.x;
                        s[2 * i + 1] += f.y;
                    }
                }
            }
        #pragma unroll
        for (int i = 0; i < 8; i++)
            yt[tc][o * 8 + i] = s[i];
    }
    __syncthreads();

    const int wid = tid >> 5, lane = tid & 31;
    float* yb = g_y + (size_t)n * 128 * YD3 + (size_t)ta * YD2 + tb * YD;
    for (int r = wid; r < 128; r += 8)
        for (int tc = lane; tc < 33; tc += 32)
            yb[(size_t)r * YD3 + tc] = yt[tc][r];
}

// ---------------------------------------------------------------------------
// Stage 2: 16^3 out tile per (n,co); 19^3 window; separable FIR + bias.
// ---------------------------------------------------------------------------
__global__ void __launch_bounds__(256)
stage2_kernel(const float* __restrict__ bias, float* __restrict__ out) {
    extern __shared__ float sm[];
    float* ys = sm;            // 19*19*19 = 6859   (reused as t2: 19*16*16)
    float* t1 = sm + 6859;     // 19*19*16 = 5776

    const int tile = blockIdx.x;
    const int u0c = (tile & 1) * 16;
    const int u0b = ((tile >> 1) & 1) * 16;
    const int u0a = (tile >> 2) * 16;
    const int co  = blockIdx.y;
    const int n   = blockIdx.z;
    const int tid = threadIdx.x;

    const float* yb = g_y + (size_t)(n * CO + co) * YD3;

    for (int e = tid; e < 6859; e += 256) {
        int c = e % 19; int r = e / 19;
        int b = r % 19; int a = r / 19;
        int ta2 = u0a - 1 + a, tb2 = u0b - 1 + b, tc2 = u0c - 1 + c;
        float v = 0.0f;
        if ((unsigned)ta2 < 33u && (unsigned)tb2 < 33u && (unsigned)tc2 < 33u)
            v = yb[(size_t)ta2 * YD2 + tb2 * YD + tc2];
        ys[e] = v;
    }
    __syncthreads();

    for (int e = tid; e < 5776; e += 256) {
        int c = e & 15; int r = e >> 4;
        int b = r % 19; int a = r / 19;
        const float* p = &ys[(a * 19 + b) * 19 + c];
        t1[e] = 0.25f * (p[0] + p[3]) + 0.75f * (p[1] + p[2]);
    }
    __syncthreads();

    for (int e = tid; e < 4864; e += 256) {
        int c = e & 15; int b = (e >> 4) & 15; int a = e >> 8;
        const float* p = &t1[(a * 19 + b) * 16 + c];
        ys[e] = 0.25f * (p[0] + p[3 * 16]) + 0.75f * (p[16] + p[2 * 16]);
    }
    __syncthreads();

    const float bv = __ldg(&bias[co]);
    for (int e = tid; e < 4096; e += 256) {
        int c = e & 15; int b = (e >> 4) & 15; int a = e >> 8;
        const float* p = &ys[a * 256 + b * 16 + c];
        float v = 0.25f * (p[0] + p[3 * 256]) + 0.75f * (p[256] + p[2 * 256]) + bv;
        out[(size_t)(n * CO + co) * 32768 +
            (size_t)(u0a + a) * 1024 + (u0b + b) * 32 + (u0c + c)] = v;
    }
}

// ---------------------------------------------------------------------------
extern "C" void kernel_launch(void* const* d_in, const int* in_sizes, int n_in,
                              void* d_out, int out_size) {
    (void)in_sizes; (void)n_in; (void)out_size;
    const float* x    = (const float*)d_in[0];
    const float* w    = (const float*)d_in[1];
    const float* bias = (const float*)d_in[2];
    float* out        = (float*)d_out;

    const int s2_smem = (6859 + 5776) * 4;   // 50540 B
    cudaFuncSetAttribute(stage2_kernel,
                         cudaFuncAttributeMaxDynamicSharedMemorySize, s2_smem);

    xa_kernel<<<dim3(128, 8, 8), 256>>>(x);
    wb_kernel<<<(27 * 128 * 256 + 255) / 256, 256>>>(w);
    gemm_kernel<<<dim3(32, 27, 8), 256>>>();
    ybuild_kernel<<<dim3(33, 33, 8), 256>>>();
    stage2_kernel<<<dim3(8, CO, 8), 256, s2_smem>>>(bias, out);
}

// round 17
// speedup vs baseline: 8.7648x; 1.0163x over previous
#include <cuda_runtime.h>
#include <cuda_fp16.h>
#include <cstdint>
#include <cstddef>

#define CI 256
#define CO 128
#define YD 33
#define YD2 (33*33)
#define YD3 (33*33*33)

// ---------------------------------------------------------------------------
// Device global scratch
// ---------------------------------------------------------------------------
__device__ __align__(16) __half g_yh[8 * 128 * YD3];               // y fp16 (~73 MB)
__device__ __align__(16) __half g_xa[(size_t)8 * 4096 * 256];      // A fp16
__device__ __align__(16) __half g_wbb[27 * 128 * 256];             // B fp16
__device__ __align__(16) __half g_Zh[(size_t)8 * 27 * 4096 * 128]; // Z fp16 (~226 MB)

// ---------------------------------------------------------------------------
// Helpers
// ---------------------------------------------------------------------------
__device__ __forceinline__ uint32_t smem_u32(const void* p) {
    uint32_t a;
    asm("{ .reg .u64 t; cvta.to.shared.u64 t, %1; cvt.u32.u64 %0, t; }" : "=r"(a) : "l"(p));
    return a;
}
#define CP16(dst_u32, src_ptr) \
    asm volatile("cp.async.cg.shared.global [%0], [%1], 16;" :: "r"(dst_u32), "l"(src_ptr))
#define CP_COMMIT() asm volatile("cp.async.commit_group;" ::: "memory")
#define CP_WAIT(n)  asm volatile("cp.async.wait_group %0;" :: "n"(n) : "memory")

__device__ __forceinline__ void mma16(float* c, const uint32_t* a, const uint32_t* b) {
    asm volatile("mma.sync.aligned.m16n8k16.row.col.f32.f16.f16.f32 "
                 "{%0,%1,%2,%3}, {%4,%5,%6,%7}, {%8,%9}, {%0,%1,%2,%3};"
                 : "+f"(c[0]), "+f"(c[1]), "+f"(c[2]), "+f"(c[3])
                 : "r"(a[0]), "r"(a[1]), "r"(a[2]), "r"(a[3]), "r"(b[0]), "r"(b[1]));
}
__device__ __forceinline__ void ldm_x4(uint32_t* r, uint32_t addr) {
    asm volatile("ldmatrix.sync.aligned.m8n8.x4.shared.b16 {%0,%1,%2,%3}, [%4];"
                 : "=r"(r[0]), "=r"(r[1]), "=r"(r[2]), "=r"(r[3]) : "r"(addr));
}

// ---------------------------------------------------------------------------
// A prep: g_xa[n][p][ci] = fp16(x[n][ci][p]).
// ---------------------------------------------------------------------------
__global__ void __launch_bounds__(256) xa_kernel(const float* __restrict__ x) {
    __shared__ float t[32][33];
    const int pt = blockIdx.x, ct = blockIdx.y, n = blockIdx.z;
    const int tx = threadIdx.x & 31, ty = threadIdx.x >> 5;
    const float* xb = x + ((size_t)n * CI + ct * 32) * 4096 + pt * 32;
    #pragma unroll
    for (int i = 0; i < 4; i++)
        t[ty + i * 8][tx] = __ldg(xb + (size_t)(ty + i * 8) * 4096 + tx);
    __syncthreads();
    __half* ob = g_xa + ((size_t)n * 4096 + pt * 32) * 256 + ct * 32;
    #pragma unroll
    for (int i = 0; i < 4; i++)
        ob[(size_t)(ty + i * 8) * 256 + tx] = __float2half_rn(t[tx][ty + i * 8]);
}

// ---------------------------------------------------------------------------
// B prep: g_wbb[j][co][ci] = fp16(w[co][ci][j]).
// ---------------------------------------------------------------------------
__global__ void __launch_bounds__(256) wb_kernel(const float* __restrict__ w) {
    int i = blockIdx.x * 256 + threadIdx.x;
    if (i >= 27 * 128 * 256) return;
    int ci = i & 255;
    int co = (i >> 8) & 127;
    int j  = i >> 15;
    g_wbb[i] = __float2half_rn(__ldg(&w[((size_t)co * CI + ci) * 27 + j]));
}

// ---------------------------------------------------------------------------
// GEMM: Zh[n][j][p][co] = fp16( sum_ci A[p][ci]*B[co][ci] ).   (proven, R15)
// ---------------------------------------------------------------------------
__global__ void __launch_bounds__(256) gemm_kernel() {
    __shared__ __align__(16) __half sA[2][128 * 40];
    __shared__ __align__(16) __half sB[2][128 * 40];

    const int tid = threadIdx.x, wid = tid >> 5, lane = tid & 31;
    const int pt = blockIdx.x, j = blockIdx.y, n = blockIdx.z;
    const int wm = wid >> 1, wn = wid & 1;
    const int g = lane >> 2, tig = lane & 3;
    const int m0 = wm * 32, n0 = wn * 64;

    const __half* Ab = g_xa + ((size_t)n * 4096 + pt * 128) * 256;
    const __half* Bb = g_wbb + (size_t)j * (128 * 256);

    const uint32_t saA = smem_u32(sA), saB = smem_u32(sB);

    const int v0 = tid, v1 = tid + 256;
    const int r0 = v0 >> 2, u0 = v0 & 3, r1 = v1 >> 2, u1 = v1 & 3;
    const uint32_t d0 = (uint32_t)(r0 * 80 + u0 * 16);
    const uint32_t d1 = (uint32_t)(r1 * 80 + u1 * 16);

    const int arow = m0 + (lane & 15);
    const int akof = (lane & 16) ? 8 : 0;
    const int brow = n0 + (lane & 7) + ((lane & 16) ? 8 : 0);
    const int bkof = (lane & 8) ? 8 : 0;

    float acc[2][8][4];
    #pragma unroll
    for (int a = 0; a < 2; a++)
        #pragma unroll
        for (int b = 0; b < 8; b++)
            #pragma unroll
            for (int c = 0; c < 4; c++) acc[a][b][c] = 0.0f;

    CP16(saA + d0, Ab + (size_t)r0 * 256 + u0 * 8);
    CP16(saA + d1, Ab + (size_t)r1 * 256 + u1 * 8);
    CP16(saB + d0, Bb + (size_t)r0 * 256 + u0 * 8);
    CP16(saB + d1, Bb + (size_t)r1 * 256 + u1 * 8);
    CP_COMMIT();

    int buf = 0;
    for (int kc = 0; kc < 8; kc++) {
        if (kc + 1 < 8) {
            const __half* As = Ab + (kc + 1) * 32;
            const __half* Bs = Bb + (kc + 1) * 32;
            const uint32_t oA = saA + (buf ^ 1) * 10240;
            const uint32_t oB = saB + (buf ^ 1) * 10240;
            CP16(oA + d0, As + (size_t)r0 * 256 + u0 * 8);
            CP16(oA + d1, As + (size_t)r1 * 256 + u1 * 8);
            CP16(oB + d0, Bs + (size_t)r0 * 256 + u0 * 8);
            CP16(oB + d1, Bs + (size_t)r1 * 256 + u1 * 8);
            CP_COMMIT();
            CP_WAIT(1);
        } else {
            CP_WAIT(0);
        }
        __syncthreads();

        const uint32_t bA = saA + buf * 10240;
        const uint32_t bB = saB + buf * 10240;
        #pragma unroll
        for (int ks = 0; ks < 2; ks++) {
            const int kb = ks * 16;
            uint32_t af[2][4];
            #pragma unroll
            for (int mt = 0; mt < 2; mt++)
                ldm_x4(af[mt], bA + (uint32_t)(((arow + mt * 16) * 40 + kb + akof) * 2));
            uint32_t bf[4][4];
            #pragma unroll
            for (int ntp = 0; ntp < 4; ntp++)
                ldm_x4(bf[ntp], bB + (uint32_t)(((brow + ntp * 16) * 40 + kb + bkof) * 2));
            #pragma unroll
            for (int nt = 0; nt < 8; nt++) {
                const uint32_t* bp = &bf[nt >> 1][(nt & 1) * 2];
                mma16(acc[0][nt], af[0], bp);
                mma16(acc[1][nt], af[1], bp);
            }
        }
        __syncthreads();
        buf ^= 1;
    }

    __half* Zb = g_Zh + ((size_t)(n * 27 + j) * 4096 + (size_t)pt * 128) * 128;
    #pragma unroll
    for (int mt = 0; mt < 2; mt++) {
        #pragma unroll
        for (int nt = 0; nt < 8; nt++) {
            int p  = m0 + mt * 16 + g;
            int co = n0 + nt * 8 + 2 * tig;
            *(__half2*)&Zb[(size_t)p * 128 + co] =
                __floats2half2_rn(acc[mt][nt][0], acc[mt][nt][1]);
            *(__half2*)&Zb[(size_t)(p + 8) * 128 + co] =
                __floats2half2_rn(acc[mt][nt][2], acc[mt][nt][3]);
        }
    }
}

// ---------------------------------------------------------------------------
// y-build v5: fp16 Z in, fp32 accumulate, fp16 y out.
// Zh index = ((f*4096 + p)*128 + co); p = pa*256 + pb*16 + pc
//   t odd  -> (j=1, p=(t-1)/2)
//   t even -> (j=0, p=(t-2)/2) if t>=2;  (j=2, p=t/2) if t<=30
// ---------------------------------------------------------------------------
__device__ __forceinline__ int plist(int t, int* j, int* p) {
    if (t & 1) { j[0] = 1; p[0] = (t - 1) >> 1; return 1; }
    int n = 0;
    if (t >= 2)  { j[n] = 0; p[n] = (t - 2) >> 1; n++; }
    if (t <= 30) { j[n] = 2; p[n] = t >> 1;       n++; }
    return n;
}

__global__ void __launch_bounds__(256) ybuild_kernel() {
    __shared__ float yt[33][133];
    const int ta = blockIdx.x, tb = blockIdx.y, n = blockIdx.z;
    const int tid  = threadIdx.x;
    const int o    = tid & 15;        // co octet: co = 8*o
    const int slot = tid >> 4;        // 0..15 tc slot

    int ja[2], pa[2], jb[2], pb[2];
    const int na = plist(ta, ja, pa);
    const int nb = plist(tb, jb, pb);

    const __half* Zn = g_Zh + (size_t)n * 27 * 4096 * 128 + o * 8;
    const __half* base[4];
    int nab = 0;
    for (int ia = 0; ia < na; ia++)
        for (int ib = 0; ib < nb; ib++)
            base[nab++] = Zn + (size_t)(ja[ia] * 3 + jb[ib]) * 3 * 524288
                             + (size_t)(pa[ia] * 256 + pb[ib] * 16) * 128;

    for (int tc = slot; tc < 33; tc += 16) {
        int jc[2], pc[2];
        int nc = plist(tc, jc, pc);
        float s[8];
        #pragma unroll
        for (int i = 0; i < 8; i++) s[i] = 0.0f;
        for (int k = 0; k < nab; k++)
            #pragma unroll
            for (int ic = 0; ic < 2; ic++) {
                if (ic < nc) {
                    uint4 v = __ldg((const uint4*)(base[k] +
                                    (size_t)jc[ic] * 524288 + (size_t)pc[ic] * 128));
                    const __half2* h = (const __half2*)&v;
                    #pragma unroll
                    for (int i = 0; i < 4; i++) {
                        float2 f = __half22float2(h[i]);
                        s[2 * i]     += f.x;
                        s[2 * i + 1] += f.y;
                    }
                }
            }
        #pragma unroll
        for (int i = 0; i < 8; i++)
            yt[tc][o * 8 + i] = s[i];
    }
    __syncthreads();

    const int wid = tid >> 5, lane = tid & 31;
    __half* yb = g_yh + (size_t)n * 128 * YD3 + (size_t)ta * YD2 + tb * YD;
    for (int r = wid; r < 128; r += 8)
        for (int tc = lane; tc < 33; tc += 32)
            yb[(size_t)r * YD3 + tc] = __float2half_rn(yt[tc][r]);
}

// ---------------------------------------------------------------------------
// Stage 2: 16^3 out tile per (n,co); 19^3 fp16 y window; fp32 FIR + bias.
// ---------------------------------------------------------------------------
__global__ void __launch_bounds__(256)
stage2_kernel(const float* __restrict__ bias, float* __restrict__ out) {
    extern __shared__ float sm[];
    float* ys = sm;            // 19*19*19 = 6859   (reused as t2: 19*16*16)
    float* t1 = sm + 6859;     // 19*19*16 = 5776

    const int tile = blockIdx.x;
    const int u0c = (tile & 1) * 16;
    const int u0b = ((tile >> 1) & 1) * 16;
    const int u0a = (tile >> 2) * 16;
    const int co  = blockIdx.y;
    const int n   = blockIdx.z;
    const int tid = threadIdx.x;

    const __half* yb = g_yh + (size_t)(n * CO + co) * YD3;

    for (int e = tid; e < 6859; e += 256) {
        int c = e % 19; int r = e / 19;
        int b = r % 19; int a = r / 19;
        int ta2 = u0a - 1 + a, tb2 = u0b - 1 + b, tc2 = u0c - 1 + c;
        float v = 0.0f;
        if ((unsigned)ta2 < 33u && (unsigned)tb2 < 33u && (unsigned)tc2 < 33u)
            v = __half2float(yb[(size_t)ta2 * YD2 + tb2 * YD + tc2]);
        ys[e] = v;
    }
    __syncthreads();

    for (int e = tid; e < 5776; e += 256) {
        int c = e & 15; int r = e >> 4;
        int b = r % 19; int a = r / 19;
        const float* p = &ys[(a * 19 + b) * 19 + c];
        t1[e] = 0.25f * (p[0] + p[3]) + 0.75f * (p[1] + p[2]);
    }
    __syncthreads();

    for (int e = tid; e < 4864; e += 256) {
        int c = e & 15; int b = (e >> 4) & 15; int a = e >> 8;
        const float* p = &t1[(a * 19 + b) * 16 + c];
        ys[e] = 0.25f * (p[0] + p[3 * 16]) + 0.75f * (p[16] + p[2 * 16]);
    }
    __syncthreads();

    const float bv = __ldg(&bias[co]);
    for (int e = tid; e < 4096; e += 256) {
        int c = e & 15; int b = (e >> 4) & 15; int a = e >> 8;
        const float* p = &ys[a * 256 + b * 16 + c];
        float v = 0.25f * (p[0] + p[3 * 256]) + 0.75f * (p[256] + p[2 * 256]) + bv;
        out[(size_t)(n * CO + co) * 32768 +
            (size_t)(u0a + a) * 1024 + (u0b + b) * 32 + (u0c + c)] = v;
    }
}

// ---------------------------------------------------------------------------
extern "C" void kernel_launch(void* const* d_in, const int* in_sizes, int n_in,
                              void* d_out, int out_size) {
    (void)in_sizes; (void)n_in; (void)out_size;
    const float* x    = (const float*)d_in[0];
    const float* w    = (const float*)d_in[1];
    const float* bias = (const float*)d_in[2];
    float* out        = (float*)d_out;

    const int s2_smem = (6859 + 5776) * 4;   // 50540 B
    cudaFuncSetAttribute(stage2_kernel,
                         cudaFuncAttributeMaxDynamicSharedMemorySize, s2_smem);

    xa_kernel<<<dim3(128, 8, 8), 256>>>(x);
    wb_kernel<<<(27 * 128 * 256 + 255) / 256, 256>>>(w);
    gemm_kernel<<<dim3(32, 27, 8), 256>>>();
    ybuild_kernel<<<dim3(33, 33, 8), 256>>>();
    stage2_kernel<<<dim3(8, CO, 8), 256, s2_smem>>>(bias, out);
}